// round 17
// baseline (speedup 1.0000x reference)
#include <cuda_runtime.h>
#include <cuda_fp16.h>
#include <math.h>

#define NMAX 100000
#define EMAX 3200000
#define CSRMAX (EMAX + 3 * NMAX + 8)
#define HID  64
#define MHID 128
#define KOUT 15
#define SCAN_BS 1024
#define NBMAX ((NMAX + SCAN_BS - 1) / SCAN_BS)

// ---- device-global scratch (no allocations allowed) ----
__device__ __half g_ah[(NMAX + 1) * HID];   // layer-1 fp16 messages; row n = zeros
__device__ __half g_ah2[(NMAX + 1) * HID];  // layer-2 fp16 messages; row n = zeros
__device__ float  g_b[NMAX * HID];          // layer-2 aggregated output (fp32)
__device__ float  g_dis[NMAX];              // (deg+1)^{-1/2}
__device__ int    g_deg[NMAX];
__device__ int    g_off[NMAX + 1];          // CSR row offsets (padded to x4)
__device__ int    g_cur[NMAX];              // scatter cursors
__device__ int    g_csr[CSRMAX];            // CSR src indices (padded with n)
__device__ int    g_bsum[NBMAX];
__device__ int    g_bar;                    // device-wide barrier counter

__device__ __forceinline__ float eluf(float v) { return v > 0.f ? v : expm1f(v); }

__device__ __forceinline__ float4 h4tof4(uint2 v) {
    float2 a = __half22float2(*reinterpret_cast<__half2*>(&v.x));
    float2 b = __half22float2(*reinterpret_cast<__half2*>(&v.y));
    return make_float4(a.x, a.y, b.x, b.y);
}

// ---------------------------------------------------------------- degrees
__global__ void k_deg_edge(const int* __restrict__ ei, int E) {
    int t = blockIdx.x * blockDim.x + threadIdx.x;
    if (t == 0) g_bar = 0;                 // reset scan barrier for this launch
    int E8 = E >> 3;
    if (t < E8) {
        int4 d0 = reinterpret_cast<const int4*>(ei + E)[2 * t];
        int4 d1 = reinterpret_cast<const int4*>(ei + E)[2 * t + 1];
        atomicAdd(&g_deg[d0.x], 1); atomicAdd(&g_deg[d0.y], 1);
        atomicAdd(&g_deg[d0.z], 1); atomicAdd(&g_deg[d0.w], 1);
        atomicAdd(&g_deg[d1.x], 1); atomicAdd(&g_deg[d1.y], 1);
        atomicAdd(&g_deg[d1.z], 1); atomicAdd(&g_deg[d1.w], 1);
    } else {
        int e = E8 * 8 + (t - E8);
        if (e < E) atomicAdd(&g_deg[ei[E + e]], 1);
    }
}

// ---------------- fused exclusive scan + offsets/dis/cursor/dummy fill
__global__ void k_scan(int n, int nb) {
    __shared__ int s[SCAN_BS];
    int t = threadIdx.x;
    int b = blockIdx.x;
    int i = b * SCAN_BS + t;
    int deg = (i < n) ? g_deg[i] : 0;
    int pdeg = (deg + 3) & ~3;
    int v = pdeg;
    s[t] = v;
    __syncthreads();
#pragma unroll
    for (int off = 1; off < SCAN_BS; off <<= 1) {
        int add = (t >= off) ? s[t - off] : 0;
        __syncthreads();
        s[t] += add;
        __syncthreads();
    }
    int exc = s[t] - v;

    if (t == 0) {
        g_bsum[b] = s[SCAN_BS - 1];
        __threadfence();
        atomicAdd(&g_bar, 1);
        while (atomicAdd(&g_bar, 0) < nb) __nanosleep(64);
    }
    __syncthreads();
    __threadfence();

    s[t] = (t < b) ? g_bsum[t] : 0;
    __syncthreads();
#pragma unroll
    for (int off = SCAN_BS / 2; off > 0; off >>= 1) {
        if (t < off) s[t] += s[t + off];
        __syncthreads();
    }
    int off = s[0] + exc;

    if (i < n) {
        g_off[i] = off;
        g_cur[i] = off;
        g_dis[i] = rsqrtf((float)(deg + 1));
        for (int j = deg; j < pdeg; j++) g_csr[off + j] = n;  // dummy -> zero row
        if (i == n - 1) g_off[n] = off + pdeg;
    }
}

// -------------------------------------------- scatter (16 edges / thread)
__global__ void k_scatter(const int* __restrict__ ei, int E) {
    int t = blockIdx.x * blockDim.x + threadIdx.x;
    int E16 = E >> 4;
    if (t < E16) {
#pragma unroll
        for (int q = 0; q < 4; q++) {
            int4 s = reinterpret_cast<const int4*>(ei)[4 * t + q];
            int4 d = reinterpret_cast<const int4*>(ei + E)[4 * t + q];
            g_csr[atomicAdd(&g_cur[d.x], 1)] = s.x;
            g_csr[atomicAdd(&g_cur[d.y], 1)] = s.y;
            g_csr[atomicAdd(&g_cur[d.z], 1)] = s.z;
            g_csr[atomicAdd(&g_cur[d.w], 1)] = s.w;
        }
    } else {
        int e = E16 * 16 + (t - E16);
        if (e < E) g_csr[atomicAdd(&g_cur[ei[E + e]], 1)] = ei[e];
    }
}

// ------------------------------------------- layer-1 input GEMM (3 -> 64)
__global__ void k_hw1(const float* __restrict__ x, const float* __restrict__ W1, int n) {
    int idx = blockIdx.x * blockDim.x + threadIdx.x;   // over (n+1)*32
    if (idx >= (n + 1) * 32) return;
    int i = idx >> 5, f = (idx & 31) * 2;
    __half2* a2 = reinterpret_cast<__half2*>(g_ah);
    __half2* c2 = reinterpret_cast<__half2*>(g_ah2);
    if (i == n) {                                      // dummy zero rows (both)
        __half2 z = __floats2half2_rn(0.f, 0.f);
        a2[idx] = z;
        c2[idx] = z;
        return;
    }
    float x0 = x[i * 3 + 0], x1 = x[i * 3 + 1], x2 = x[i * 3 + 2];
    float d = g_dis[i];
    float v0 = (x0 * W1[f]     + x1 * W1[HID + f]     + x2 * W1[2 * HID + f]) * d;
    float v1 = (x0 * W1[f + 1] + x1 * W1[HID + f + 1] + x2 * W1[2 * HID + f + 1]) * d;
    a2[idx] = __floats2half2_rn(v0, v1);
}

// ===== fused: aggr(layer1 from g_ah) + per-warp GEMM(W2) -> g_ah2 (fp16) ===
// W2 staged once (one syncthreads BEFORE the gather loop); warps independent
// afterwards. GEMM math fills aggr's ~50% idle issue slots.
__global__ void k_aggr_gemm(const float* __restrict__ bias,
                            const float* __restrict__ W, int n) {
    __shared__ float Ws[HID * HID];        // 16 KB
    __shared__ float hs[8][HID];           // per-warp row buffer (2 KB)
    int tid = threadIdx.x;
    for (int i = tid; i < HID * HID; i += 256) Ws[i] = W[i];
    __syncthreads();

    int gw = (blockIdx.x * blockDim.x + tid) >> 5;
    if (gw >= n) return;
    int lane = tid & 31;
    int wid = tid >> 5;
    const uint2* __restrict__ ah4 = reinterpret_cast<const uint2*>(g_ah);
    int half_ = lane >> 4;
    int fo = lane & 15;

    float4 acc = make_float4(0.f, 0.f, 0.f, 0.f);
    if (half_ == 0) acc = h4tof4(ah4[gw * 16 + fo]);   // self loop (fp32)

    int j = g_off[gw];
    int end = g_off[gw + 1];
    for (; j + 8 <= end; j += 8) {
        int4 i0 = *reinterpret_cast<const int4*>(&g_csr[j]);
        int4 i1 = *reinterpret_cast<const int4*>(&g_csr[j + 4]);
        int sA = half_ ? i0.y : i0.x;
        int sB = half_ ? i0.w : i0.z;
        int sC = half_ ? i1.y : i1.x;
        int sD = half_ ? i1.w : i1.z;
        uint2 vA = ah4[sA * 16 + fo];
        uint2 vB = ah4[sB * 16 + fo];
        uint2 vC = ah4[sC * 16 + fo];
        uint2 vD = ah4[sD * 16 + fo];
        __half2 p0 = __hadd2(__hadd2(*reinterpret_cast<__half2*>(&vA.x),
                                     *reinterpret_cast<__half2*>(&vB.x)),
                             __hadd2(*reinterpret_cast<__half2*>(&vC.x),
                                     *reinterpret_cast<__half2*>(&vD.x)));
        __half2 p1 = __hadd2(__hadd2(*reinterpret_cast<__half2*>(&vA.y),
                                     *reinterpret_cast<__half2*>(&vB.y)),
                             __hadd2(*reinterpret_cast<__half2*>(&vC.y),
                                     *reinterpret_cast<__half2*>(&vD.y)));
        float2 f0 = __half22float2(p0);
        float2 f1 = __half22float2(p1);
        acc.x += f0.x; acc.y += f0.y; acc.z += f1.x; acc.w += f1.y;
    }
    if (j < end) {                           // remainder exactly 4
        int4 i0 = *reinterpret_cast<const int4*>(&g_csr[j]);
        int sA = half_ ? i0.y : i0.x;
        int sB = half_ ? i0.w : i0.z;
        uint2 vA = ah4[sA * 16 + fo];
        uint2 vB = ah4[sB * 16 + fo];
        __half2 p0 = __hadd2(*reinterpret_cast<__half2*>(&vA.x),
                             *reinterpret_cast<__half2*>(&vB.x));
        __half2 p1 = __hadd2(*reinterpret_cast<__half2*>(&vA.y),
                             *reinterpret_cast<__half2*>(&vB.y));
        float2 f0 = __half22float2(p0);
        float2 f1 = __half22float2(p1);
        acc.x += f0.x; acc.y += f0.y; acc.z += f1.x; acc.w += f1.y;
    }
    acc.x += __shfl_down_sync(0xffffffffu, acc.x, 16);
    acc.y += __shfl_down_sync(0xffffffffu, acc.y, 16);
    acc.z += __shfl_down_sync(0xffffffffu, acc.z, 16);
    acc.w += __shfl_down_sync(0xffffffffu, acc.w, 16);

    float d = g_dis[gw];
    if (lane < 16) {                         // h = elu(aggr*dis + b1) -> smem
        int f = lane * 4;
        hs[wid][f]     = eluf(acc.x * d + bias[f]);
        hs[wid][f + 1] = eluf(acc.y * d + bias[f + 1]);
        hs[wid][f + 2] = eluf(acc.z * d + bias[f + 2]);
        hs[wid][f + 3] = eluf(acc.w * d + bias[f + 3]);
    }
    __syncwarp();

    // per-warp GEMM: o[2] per lane; message = o * dis (pre-scaled fp16)
    float o0 = 0.f, o1 = 0.f;
#pragma unroll 16
    for (int k = 0; k < HID; k++) {
        float hv = hs[wid][k];
        float2 w = *reinterpret_cast<const float2*>(&Ws[k * HID + lane * 2]);
        o0 += hv * w.x;
        o1 += hv * w.y;
    }
    reinterpret_cast<__half2*>(g_ah2)[gw * 32 + lane] =
        __floats2half2_rn(o0 * d, o1 * d);
}

// ------------------- aggr pass 2: gather g_ah2 -> g_b (fp32, R10 form)
__global__ void k_aggr2(int n) {
    int gw = (blockIdx.x * blockDim.x + threadIdx.x) >> 5;
    if (gw >= n) return;
    int lane = threadIdx.x & 31;
    const uint2* __restrict__ ah4 = reinterpret_cast<const uint2*>(g_ah2);
    int half_ = lane >> 4;
    int fo = lane & 15;

    float4 acc = make_float4(0.f, 0.f, 0.f, 0.f);
    if (half_ == 0) acc = h4tof4(ah4[gw * 16 + fo]);   // self loop (fp32)

    int j = g_off[gw];
    int end = g_off[gw + 1];
    for (; j + 8 <= end; j += 8) {
        int4 i0 = *reinterpret_cast<const int4*>(&g_csr[j]);
        int4 i1 = *reinterpret_cast<const int4*>(&g_csr[j + 4]);
        int sA = half_ ? i0.y : i0.x;
        int sB = half_ ? i0.w : i0.z;
        int sC = half_ ? i1.y : i1.x;
        int sD = half_ ? i1.w : i1.z;
        uint2 vA = ah4[sA * 16 + fo];
        uint2 vB = ah4[sB * 16 + fo];
        uint2 vC = ah4[sC * 16 + fo];
        uint2 vD = ah4[sD * 16 + fo];
        __half2 p0 = __hadd2(__hadd2(*reinterpret_cast<__half2*>(&vA.x),
                                     *reinterpret_cast<__half2*>(&vB.x)),
                             __hadd2(*reinterpret_cast<__half2*>(&vC.x),
                                     *reinterpret_cast<__half2*>(&vD.x)));
        __half2 p1 = __hadd2(__hadd2(*reinterpret_cast<__half2*>(&vA.y),
                                     *reinterpret_cast<__half2*>(&vB.y)),
                             __hadd2(*reinterpret_cast<__half2*>(&vC.y),
                                     *reinterpret_cast<__half2*>(&vD.y)));
        float2 f0 = __half22float2(p0);
        float2 f1 = __half22float2(p1);
        acc.x += f0.x; acc.y += f0.y; acc.z += f1.x; acc.w += f1.y;
    }
    if (j < end) {
        int4 i0 = *reinterpret_cast<const int4*>(&g_csr[j]);
        int sA = half_ ? i0.y : i0.x;
        int sB = half_ ? i0.w : i0.z;
        uint2 vA = ah4[sA * 16 + fo];
        uint2 vB = ah4[sB * 16 + fo];
        __half2 p0 = __hadd2(*reinterpret_cast<__half2*>(&vA.x),
                             *reinterpret_cast<__half2*>(&vB.x));
        __half2 p1 = __hadd2(*reinterpret_cast<__half2*>(&vA.y),
                             *reinterpret_cast<__half2*>(&vB.y));
        float2 f0 = __half22float2(p0);
        float2 f1 = __half22float2(p1);
        acc.x += f0.x; acc.y += f0.y; acc.z += f1.x; acc.w += f1.y;
    }
    acc.x += __shfl_down_sync(0xffffffffu, acc.x, 16);
    acc.y += __shfl_down_sync(0xffffffffu, acc.y, 16);
    acc.z += __shfl_down_sync(0xffffffffu, acc.z, 16);
    acc.w += __shfl_down_sync(0xffffffffu, acc.w, 16);

    if (lane < 16) {
        float d = g_dis[gw];
        *reinterpret_cast<float4*>(&g_b[gw * HID + lane * 4]) =
            make_float4(acc.x * d, acc.y * d, acc.z * d, acc.w * d);
    }
}

// ---------------- fused MLP (32 rows/block, dynamic smem) + softmax
#define SMEM_MLP_FLOATS (32 * HID + HID * MHID + 32 * MHID + MHID * KOUT + KOUT)
__global__ void k_mlp(const float* __restrict__ b2,
                      const float* __restrict__ Wm1,
                      const float* __restrict__ bm1,
                      const float* __restrict__ Wm2,
                      const float* __restrict__ bm2,
                      float* __restrict__ out, int n) {
    extern __shared__ float sm[];
    float* As  = sm;
    float* Ws  = As + 32 * HID;
    float* Hs  = Ws + HID * MHID;
    float* W2s = Hs + 32 * MHID;
    float* b2s = W2s + MHID * KOUT;
    int tid = threadIdx.x;
    int row0 = blockIdx.x * 32;

    for (int i = tid; i < HID * MHID; i += 256) Ws[i] = Wm1[i];
    for (int i = tid; i < MHID * KOUT; i += 256) W2s[i] = Wm2[i];
    if (tid < KOUT) b2s[tid] = bm2[tid];
    for (int i = tid; i < 32 * HID; i += 256) {
        int r = i >> 6, k = i & 63;
        int row = row0 + r;
        As[i] = (row < n) ? eluf(g_b[row * HID + k] + b2[k]) : 0.f;
    }
    __syncthreads();

    {
        int fx = (tid & 31) * 4;
        int r0 = (tid >> 5) * 4;
        float4 a0 = make_float4(0.f, 0.f, 0.f, 0.f);
        float4 a1 = make_float4(0.f, 0.f, 0.f, 0.f);
        float4 a2 = make_float4(0.f, 0.f, 0.f, 0.f);
        float4 a3 = make_float4(0.f, 0.f, 0.f, 0.f);
#pragma unroll 8
        for (int k = 0; k < HID; k++) {
            float4 w = *reinterpret_cast<const float4*>(&Ws[k * MHID + fx]);
            float v0 = As[(r0 + 0) * HID + k];
            float v1 = As[(r0 + 1) * HID + k];
            float v2 = As[(r0 + 2) * HID + k];
            float v3 = As[(r0 + 3) * HID + k];
            a0.x += v0 * w.x; a0.y += v0 * w.y; a0.z += v0 * w.z; a0.w += v0 * w.w;
            a1.x += v1 * w.x; a1.y += v1 * w.y; a1.z += v1 * w.z; a1.w += v1 * w.w;
            a2.x += v2 * w.x; a2.y += v2 * w.y; a2.z += v2 * w.z; a2.w += v2 * w.w;
            a3.x += v3 * w.x; a3.y += v3 * w.y; a3.z += v3 * w.z; a3.w += v3 * w.w;
        }
        float4 bb = *reinterpret_cast<const float4*>(&bm1[fx]);
        *reinterpret_cast<float4*>(&Hs[(r0 + 0) * MHID + fx]) =
            make_float4(eluf(a0.x + bb.x), eluf(a0.y + bb.y), eluf(a0.z + bb.z), eluf(a0.w + bb.w));
        *reinterpret_cast<float4*>(&Hs[(r0 + 1) * MHID + fx]) =
            make_float4(eluf(a1.x + bb.x), eluf(a1.y + bb.y), eluf(a1.z + bb.z), eluf(a1.w + bb.w));
        *reinterpret_cast<float4*>(&Hs[(r0 + 2) * MHID + fx]) =
            make_float4(eluf(a2.x + bb.x), eluf(a2.y + bb.y), eluf(a2.z + bb.z), eluf(a2.w + bb.w));
        *reinterpret_cast<float4*>(&Hs[(r0 + 3) * MHID + fx]) =
            make_float4(eluf(a3.x + bb.x), eluf(a3.y + bb.y), eluf(a3.z + bb.z), eluf(a3.w + bb.w));
    }
    __syncthreads();

    int wid = tid >> 5;
    int lane = tid & 31;
#pragma unroll
    for (int rr = 0; rr < 4; rr++) {
        int r = wid * 4 + rr;
        int row = row0 + r;
        float p[KOUT];
#pragma unroll
        for (int c = 0; c < KOUT; c++) p[c] = 0.f;
#pragma unroll
        for (int jj = 0; jj < 4; jj++) {
            int k = lane + 32 * jj;
            float hv = Hs[r * MHID + k];
#pragma unroll
            for (int c = 0; c < KOUT; c++) p[c] += hv * W2s[k * KOUT + c];
        }
#pragma unroll
        for (int off = 16; off > 0; off >>= 1)
#pragma unroll
            for (int c = 0; c < KOUT; c++)
                p[c] += __shfl_xor_sync(0xffffffffu, p[c], off);

        float mx = -1e30f;
#pragma unroll
        for (int c = 0; c < KOUT; c++) { p[c] += b2s[c]; mx = fmaxf(mx, p[c]); }
        float s = 0.f;
#pragma unroll
        for (int c = 0; c < KOUT; c++) { p[c] = expf(p[c] - mx); s += p[c]; }
        float inv = 1.f / s;
        if (row < n && lane < KOUT) out[row * KOUT + lane] = p[lane] * inv;
    }
}

// ---------------------------------------------------------------- launch
extern "C" void kernel_launch(void* const* d_in, const int* in_sizes, int n_in,
                              void* d_out, int out_size) {
    const float* x   = (const float*)d_in[0];
    const int*   ei  = (const int*)  d_in[1];
    const float* W1  = (const float*)d_in[2];
    const float* b1  = (const float*)d_in[3];
    const float* W2  = (const float*)d_in[4];
    const float* b2  = (const float*)d_in[5];
    const float* Wm1 = (const float*)d_in[6];
    const float* bm1 = (const float*)d_in[7];
    const float* Wm2 = (const float*)d_in[8];
    const float* bm2 = (const float*)d_in[9];
    float* out = (float*)d_out;

    int n = in_sizes[0] / 3;
    int E = in_sizes[1] / 2;
    int nb = (n + SCAN_BS - 1) / SCAN_BS;
    int E8 = E >> 3;
    int degThreads = E8 + (E - E8 * 8);
    int E16 = E >> 4;
    int scatThreads = E16 + (E - E16 * 16);

    static void* deg_ptr = nullptr;
    static cudaStream_t s2 = nullptr;
    static cudaEvent_t evFork = nullptr, evJoin = nullptr;
    static int init_done = 0;
    if (!init_done) {
        cudaFuncSetAttribute(k_mlp, cudaFuncAttributeMaxDynamicSharedMemorySize,
                             SMEM_MLP_FLOATS * (int)sizeof(float));
        cudaGetSymbolAddress(&deg_ptr, g_deg);
        cudaStreamCreateWithFlags(&s2, cudaStreamNonBlocking);
        cudaEventCreateWithFlags(&evFork, cudaEventDisableTiming);
        cudaEventCreateWithFlags(&evJoin, cudaEventDisableTiming);
        init_done = 1;
    }

    // CSR build front half (main stream)
    cudaMemsetAsync(deg_ptr, 0, n * sizeof(int));
    k_deg_edge<<<(degThreads + 255) / 256, 256>>>(ei, E);
    k_scan<<<nb, SCAN_BS>>>(n, nb);

    // fork: scatter on s2, hw1 on main stream (independent)
    cudaEventRecord(evFork, 0);
    cudaStreamWaitEvent(s2, evFork, 0);
    k_scatter<<<(scatThreads + 255) / 256, 256, 0, s2>>>(ei, E);
    k_hw1<<<((n + 1) * 32 + 255) / 256, 256>>>(x, W1, n);
    cudaEventRecord(evJoin, s2);
    cudaStreamWaitEvent(0, evJoin, 0);

    // fused: aggr(layer1) + per-warp GEMM(W2) -> g_ah2
    int aggr_blocks = (n * 32 + 255) / 256;
    k_aggr_gemm<<<aggr_blocks, 256>>>(b1, W2, n);

    // aggr pass 2 -> g_b
    k_aggr2<<<aggr_blocks, 256>>>(n);

    // fused MLP + softmax
    k_mlp<<<(n + 31) / 32, 256, SMEM_MLP_FLOATS * (int)sizeof(float)>>>(
        b2, Wm1, bm1, Wm2, bm2, out, n);
}